// round 2
// baseline (speedup 1.0000x reference)
#include <cuda_runtime.h>

#define NN   50000
#define NE   800000
#define INC  8
#define OUTC 16
#define CDIM 256      // HEADS*HID
#define FDIM 128
#define CAP  512

// ---------------- scratch (static device globals; no allocs) ----------------
__device__ int   g_deg[NN];
__device__ int   g_off[NN + 1];
__device__ int   g_part[32];
__device__ int   g_cur[NN];
__device__ int   g_ssrc[NE];
__device__ float g_agg[NN * OUTC];
__device__ float g_h[NN * OUTC];
__device__ float g_gmat[(size_t)NN * CDIM];
__device__ float g_as[NN * 4];
__device__ float g_ad[NN * 4];
__device__ float g_outg[(size_t)NN * CDIM];

// ---------------- init ----------------
__global__ void k_init() {
    int i = blockIdx.x * blockDim.x + threadIdx.x;
    int stride = gridDim.x * blockDim.x;
    for (int j = i; j < NN * OUTC; j += stride) g_agg[j] = 0.f;
    for (int j = i; j < NN; j += stride) g_deg[j] = 0;
}

// ---------------- degree histogram ----------------
__global__ void k_hist(const int* __restrict__ ei) {
    int e = blockIdx.x * blockDim.x + threadIdx.x;
    if (e >= NE) return;
    int d = ei[NE + e];
    atomicAdd(&g_deg[d], 1);
}

// ---------------- scan (3 kernels) ----------------
// scanA: 13 blocks * 256 threads * 16 elems = 53248 >= NN
__global__ void k_scanA() {
    __shared__ int sh[256];
    int t = threadIdx.x, b = blockIdx.x;
    int base = (b * 256 + t) * 16;
    int local[16];
    int s = 0;
#pragma unroll
    for (int i = 0; i < 16; i++) {
        int idx = base + i;
        int v = (idx < NN) ? g_deg[idx] : 0;
        local[i] = v; s += v;
    }
    sh[t] = s;
    __syncthreads();
    for (int ofs = 1; ofs < 256; ofs <<= 1) {
        int v = (t >= ofs) ? sh[t - ofs] : 0;
        __syncthreads();
        sh[t] += v;
        __syncthreads();
    }
    int excl = sh[t] - s;
    if (t == 255) g_part[b] = sh[255];
    int run = excl;
#pragma unroll
    for (int i = 0; i < 16; i++) {
        int idx = base + i;
        if (idx < NN) g_off[idx] = run;
        run += local[i];
    }
}

__global__ void k_scanB(int nb) {
    if (threadIdx.x == 0) {
        int s = 0;
        for (int i = 0; i < nb; i++) { int v = g_part[i]; g_part[i] = s; s += v; }
        g_off[NN] = s;   // == NE
    }
}

__global__ void k_scanC() {
    int i = blockIdx.x * blockDim.x + threadIdx.x;
    if (i >= NN) return;
    int v = g_off[i] + g_part[i >> 12];
    g_off[i] = v;
    g_cur[i] = v;
}

// ---------------- CSR scatter ----------------
__global__ void k_scatter(const int* __restrict__ ei) {
    int e = blockIdx.x * blockDim.x + threadIdx.x;
    if (e >= NE) return;
    int s = ei[e];
    int d = ei[NE + e];
    int p = atomicAdd(&g_cur[d], 1);
    g_ssrc[p] = s;
}

// ---------------- NNConv messages + scatter-add ----------------
__global__ void k_nnconv(const float* __restrict__ x, const int* __restrict__ ei,
                         const float* __restrict__ ea, const float* __restrict__ mlpw,
                         const float* __restrict__ mlpb) {
    __shared__ float sw[INC * 128];
    __shared__ float sb[128];
    for (int i = threadIdx.x; i < INC * 128; i += blockDim.x) sw[i] = mlpw[i];
    for (int i = threadIdx.x; i < 128; i += blockDim.x) sb[i] = mlpb[i];
    __syncthreads();
    int e = blockIdx.x * blockDim.x + threadIdx.x;
    if (e >= NE) return;
    int s = ei[e];
    int d = ei[NE + e];
    float eav[8], xv[8];
    float4 a0 = *(const float4*)(ea + (size_t)e * 8);
    float4 a1 = *(const float4*)(ea + (size_t)e * 8 + 4);
    eav[0] = a0.x; eav[1] = a0.y; eav[2] = a0.z; eav[3] = a0.w;
    eav[4] = a1.x; eav[5] = a1.y; eav[6] = a1.z; eav[7] = a1.w;
    float4 x0 = *(const float4*)(x + (size_t)s * 8);
    float4 x1 = *(const float4*)(x + (size_t)s * 8 + 4);
    xv[0] = x0.x; xv[1] = x0.y; xv[2] = x0.z; xv[3] = x0.w;
    xv[4] = x1.x; xv[5] = x1.y; xv[6] = x1.z; xv[7] = x1.w;
#pragma unroll
    for (int o = 0; o < OUTC; o++) {
        float m = 0.f;
#pragma unroll
        for (int i = 0; i < 8; i++) {
            float w = sb[i * 16 + o];
#pragma unroll
            for (int f = 0; f < 8; f++) w += eav[f] * sw[f * 128 + i * 16 + o];
            m += xv[i] * w;
        }
        atomicAdd(&g_agg[d * OUTC + o], m);
    }
}

// ---------------- h = relu(x@root + agg + bias) ----------------
__global__ void k_h(const float* __restrict__ x, const float* __restrict__ root,
                    const float* __restrict__ bias) {
    int idx = blockIdx.x * blockDim.x + threadIdx.x;
    if (idx >= NN * OUTC) return;
    int n = idx >> 4, o = idx & 15;
    float v = g_agg[idx] + bias[o];
    const float* xr = x + (size_t)n * 8;
#pragma unroll
    for (int i = 0; i < 8; i++) v += xr[i] * root[i * 16 + o];
    g_h[idx] = fmaxf(v, 0.f);
}

// ---------------- g = h @ gat_lin, 16 nodes per block ----------------
__global__ void k_g(const float* __restrict__ lin) {
    __shared__ float slin[16 * CDIM];
    __shared__ float shh[16 * 16];
    int tid = threadIdx.x;
    for (int i = tid; i < 16 * CDIM; i += 256) slin[i] = lin[i];
    int n0 = blockIdx.x * 16;
    {
        int m = tid >> 4, k = tid & 15;
        int n = n0 + m;
        shh[tid] = (n < NN) ? g_h[n * OUTC + k] : 0.f;
    }
    __syncthreads();
    float acc[16];
#pragma unroll
    for (int m = 0; m < 16; m++) acc[m] = 0.f;
#pragma unroll
    for (int k = 0; k < 16; k++) {
        float w = slin[k * CDIM + tid];
#pragma unroll
        for (int m = 0; m < 16; m++) acc[m] += shh[m * 16 + k] * w;
    }
#pragma unroll
    for (int m = 0; m < 16; m++) {
        int n = n0 + m;
        if (n < NN) g_gmat[(size_t)n * CDIM + tid] = acc[m];
    }
}

// ---------------- per-node attention logit coefs ----------------
__global__ void k_att(const float* __restrict__ atts, const float* __restrict__ attd) {
    int gt = blockIdx.x * blockDim.x + threadIdx.x;
    int gw = gt >> 5, lane = gt & 31;
    if (gw >= NN * 4) return;
    int n = gw >> 2, h = gw & 3;
    const float* gr = g_gmat + (size_t)n * CDIM + h * 64;
    float s1 = gr[lane] * atts[h * 64 + lane] + gr[lane + 32] * atts[h * 64 + lane + 32];
    float s2 = gr[lane] * attd[h * 64 + lane] + gr[lane + 32] * attd[h * 64 + lane + 32];
#pragma unroll
    for (int o = 16; o; o >>= 1) {
        s1 += __shfl_xor_sync(0xffffffffu, s1, o);
        s2 += __shfl_xor_sync(0xffffffffu, s2, o);
    }
    if (lane == 0) { g_as[n * 4 + h] = s1; g_ad[n * 4 + h] = s2; }
}

// ---------------- GAT softmax + aggregate, one block per dst node ----------------
__device__ __forceinline__ float leaky(float v) { return v > 0.f ? v : 0.2f * v; }

__global__ void k_gatagg(const float* __restrict__ gbias) {
    __shared__ int   sh_src[CAP];
    __shared__ float sh_e[CAP * 4];
    __shared__ float sred[32];
    __shared__ float smax[4], sinv[4];
    int tid = threadIdx.x, lane = tid & 31, warp = tid >> 5;
    int n = blockIdx.x;
    int beg = g_off[n];
    int deg = g_off[n + 1] - beg;
    float4 adv = *(const float4*)(g_ad + n * 4);
    float ad[4] = {adv.x, adv.y, adv.z, adv.w};
    int hh = tid >> 6;
    float acc = 0.f;

    if (deg <= CAP) {
        float lm[4] = {-1e30f, -1e30f, -1e30f, -1e30f};
        for (int j = tid; j < deg; j += 256) {
            int s = g_ssrc[beg + j];
            sh_src[j] = s;
            float4 av = *(const float4*)(g_as + s * 4);
            float ev[4] = {av.x + ad[0], av.y + ad[1], av.z + ad[2], av.w + ad[3]};
#pragma unroll
            for (int h = 0; h < 4; h++) {
                float e = leaky(ev[h]);
                sh_e[j * 4 + h] = e;
                lm[h] = fmaxf(lm[h], e);
            }
        }
#pragma unroll
        for (int o = 16; o; o >>= 1)
#pragma unroll
            for (int h = 0; h < 4; h++) lm[h] = fmaxf(lm[h], __shfl_xor_sync(0xffffffffu, lm[h], o));
        if (lane == 0)
#pragma unroll
            for (int h = 0; h < 4; h++) sred[warp * 4 + h] = lm[h];
        __syncthreads();
        if (tid < 4) {
            float m = sred[tid];
            for (int w = 1; w < 8; w++) m = fmaxf(m, sred[w * 4 + tid]);
            smax[tid] = m;
        }
        __syncthreads();
        float ls[4] = {0.f, 0.f, 0.f, 0.f};
        for (int j = tid; j < deg; j += 256) {
#pragma unroll
            for (int h = 0; h < 4; h++) {
                float ex = __expf(sh_e[j * 4 + h] - smax[h]);
                sh_e[j * 4 + h] = ex;
                ls[h] += ex;
            }
        }
#pragma unroll
        for (int o = 16; o; o >>= 1)
#pragma unroll
            for (int h = 0; h < 4; h++) ls[h] += __shfl_xor_sync(0xffffffffu, ls[h], o);
        __syncthreads();  // protect sred reuse
        if (lane == 0)
#pragma unroll
            for (int h = 0; h < 4; h++) sred[warp * 4 + h] = ls[h];
        __syncthreads();
        if (tid < 4) {
            float s = 0.f;
            for (int w = 0; w < 8; w++) s += sred[w * 4 + tid];
            sinv[tid] = 1.f / (s + 1e-16f);
        }
        __syncthreads();
#pragma unroll 4
        for (int j = 0; j < deg; j++)
            acc += sh_e[j * 4 + hh] * g_gmat[(size_t)sh_src[j] * CDIM + tid];
    } else {
        // rare fallback: degree > CAP
        float lm[4] = {-1e30f, -1e30f, -1e30f, -1e30f};
        for (int j = tid; j < deg; j += 256) {
            int s = g_ssrc[beg + j];
            float4 av = *(const float4*)(g_as + s * 4);
            lm[0] = fmaxf(lm[0], leaky(av.x + ad[0]));
            lm[1] = fmaxf(lm[1], leaky(av.y + ad[1]));
            lm[2] = fmaxf(lm[2], leaky(av.z + ad[2]));
            lm[3] = fmaxf(lm[3], leaky(av.w + ad[3]));
        }
#pragma unroll
        for (int o = 16; o; o >>= 1)
#pragma unroll
            for (int h = 0; h < 4; h++) lm[h] = fmaxf(lm[h], __shfl_xor_sync(0xffffffffu, lm[h], o));
        if (lane == 0)
#pragma unroll
            for (int h = 0; h < 4; h++) sred[warp * 4 + h] = lm[h];
        __syncthreads();
        if (tid < 4) {
            float m = sred[tid];
            for (int w = 1; w < 8; w++) m = fmaxf(m, sred[w * 4 + tid]);
            smax[tid] = m;
        }
        __syncthreads();
        float ls[4] = {0.f, 0.f, 0.f, 0.f};
        for (int j = tid; j < deg; j += 256) {
            int s = g_ssrc[beg + j];
            float4 av = *(const float4*)(g_as + s * 4);
            ls[0] += __expf(leaky(av.x + ad[0]) - smax[0]);
            ls[1] += __expf(leaky(av.y + ad[1]) - smax[1]);
            ls[2] += __expf(leaky(av.z + ad[2]) - smax[2]);
            ls[3] += __expf(leaky(av.w + ad[3]) - smax[3]);
        }
#pragma unroll
        for (int o = 16; o; o >>= 1)
#pragma unroll
            for (int h = 0; h < 4; h++) ls[h] += __shfl_xor_sync(0xffffffffu, ls[h], o);
        __syncthreads();
        if (lane == 0)
#pragma unroll
            for (int h = 0; h < 4; h++) sred[warp * 4 + h] = ls[h];
        __syncthreads();
        if (tid < 4) {
            float s = 0.f;
            for (int w = 0; w < 8; w++) s += sred[w * 4 + tid];
            sinv[tid] = 1.f / (s + 1e-16f);
        }
        __syncthreads();
        for (int base = 0; base < deg; base += 256) {
            int cnt = min(256, deg - base);
            if (tid < cnt) {
                int s = g_ssrc[beg + base + tid];
                sh_src[tid] = s;
                float4 av = *(const float4*)(g_as + s * 4);
                sh_e[tid * 4 + 0] = __expf(leaky(av.x + ad[0]) - smax[0]);
                sh_e[tid * 4 + 1] = __expf(leaky(av.y + ad[1]) - smax[1]);
                sh_e[tid * 4 + 2] = __expf(leaky(av.z + ad[2]) - smax[2]);
                sh_e[tid * 4 + 3] = __expf(leaky(av.w + ad[3]) - smax[3]);
            }
            __syncthreads();
            for (int j = 0; j < cnt; j++)
                acc += sh_e[j * 4 + hh] * g_gmat[(size_t)sh_src[j] * CDIM + tid];
            __syncthreads();
        }
    }
    acc *= sinv[hh];
    g_outg[(size_t)n * CDIM + tid] = fmaxf(acc + gbias[tid], 0.f);
}

// ---------------- final linear: [NN,256] @ [256,128] + b ----------------
__global__ void k_fc(const float* __restrict__ w, const float* __restrict__ b,
                     float* __restrict__ out) {
    __shared__ float sx[32 * CDIM];
    int tid = threadIdx.x;
    int n0 = blockIdx.x * 32;
    const float4* src = (const float4*)(g_outg + (size_t)n0 * CDIM);
    float4* dst4 = (float4*)sx;
    for (int i = tid; i < 32 * CDIM / 4; i += 256) {
        int n = n0 + (i >> 6);
        dst4[i] = (n < NN) ? src[i] : make_float4(0.f, 0.f, 0.f, 0.f);
    }
    __syncthreads();
    int half = tid >> 7, o = tid & 127;
    float acc[16];
#pragma unroll
    for (int m = 0; m < 16; m++) acc[m] = 0.f;
    const float* xb = sx + half * 16 * CDIM;
#pragma unroll 8
    for (int k = 0; k < CDIM; k++) {
        float wv = w[k * FDIM + o];
#pragma unroll
        for (int m = 0; m < 16; m++) acc[m] += xb[m * CDIM + k] * wv;
    }
    float bias = b[o];
#pragma unroll
    for (int m = 0; m < 16; m++) {
        int n = n0 + half * 16 + m;
        if (n < NN) out[(size_t)n * FDIM + o] = acc[m] + bias;
    }
}

// ---------------- launcher ----------------
extern "C" void kernel_launch(void* const* d_in, const int* in_sizes, int n_in,
                              void* d_out, int out_size) {
    const float* x        = (const float*)d_in[0];
    const int*   ei       = (const int*)d_in[1];      // int32: JAX x64 disabled
    const float* ea       = (const float*)d_in[2];
    const float* ecc_root = (const float*)d_in[3];
    const float* ecc_bias = (const float*)d_in[4];
    const float* mlp_w    = (const float*)d_in[5];
    const float* mlp_b    = (const float*)d_in[6];
    const float* gat_lin  = (const float*)d_in[7];
    const float* att_src  = (const float*)d_in[8];
    const float* att_dst  = (const float*)d_in[9];
    const float* gat_bias = (const float*)d_in[10];
    const float* fc_w     = (const float*)d_in[11];
    const float* fc_b     = (const float*)d_in[12];
    float*       out      = (float*)d_out;

    const int EB = (NE + 255) / 256;

    k_init<<<512, 256>>>();
    k_hist<<<EB, 256>>>(ei);
    k_scanA<<<13, 256>>>();
    k_scanB<<<1, 32>>>(13);
    k_scanC<<<(NN + 255) / 256, 256>>>();
    k_scatter<<<EB, 256>>>(ei);
    k_nnconv<<<EB, 256>>>(x, ei, ea, mlp_w, mlp_b);
    k_h<<<(NN * OUTC + 255) / 256, 256>>>(x, ecc_root, ecc_bias);
    k_g<<<(NN + 15) / 16, 256>>>(gat_lin);
    k_att<<<(NN * 4 * 32) / 256, 256>>>(att_src, att_dst);
    k_gatagg<<<NN, 256>>>(gat_bias);
    k_fc<<<(NN + 31) / 32, 256>>>(fc_w, fc_b, out);
}